// round 1
// baseline (speedup 1.0000x reference)
#include <cuda_runtime.h>
#include <math.h>

#define TT 256
#define OBS 512
#define HID 1024
#define MSG 128
#define PED 128

// ---- device scratch (static; no allocations) ----
__device__ float g_q[HID * MSG];          // 512 KB : q = pos_emb @ Wq^T + bq
__device__ float g_K[TT * OBS * MSG];     // 64 MB  : per-step key messages
__device__ float g_x[TT * OBS];           // normalized obs
__device__ float g_act[TT * OBS];         // b_ih + b_hh + W_ih[:,1:] @ a_t  (512 = 4*PED)
__device__ float g_WhhT[PED * 512];       // W_hh transposed [k][j]
__device__ float g_WkT[PED * MSG];        // W_k transposed  [k][j]
__device__ float g_wih0[512];             // W_ih[:,0]

__device__ __forceinline__ float fsig(float x) {
    return 1.0f / (1.0f + __expf(-x));
}
__device__ __forceinline__ float ftanh(float x) {
    // accurate fast tanh: 1 EX2 + 1 RCP, rel err ~1e-6, safe at large |x|
    float t = __expf(-2.0f * fabsf(x));
    float r = (1.0f - t) / (1.0f + t);
    return copysignf(r, x);
}

// ---------------------------------------------------------------------------
// prep: normalize obs, action term, transposes, wih0
// grid: 512 x 256 = 131072 threads
// ---------------------------------------------------------------------------
__global__ void prep_kernel(const float* __restrict__ obs,
                            const float* __restrict__ prev_act,
                            const float* __restrict__ in_shift,
                            const float* __restrict__ in_scale,
                            const float* __restrict__ W_ih,
                            const float* __restrict__ b_ih,
                            const float* __restrict__ W_hh,
                            const float* __restrict__ b_hh,
                            const float* __restrict__ Wk) {
    int idx = blockIdx.x * blockDim.x + threadIdx.x;  // 0..131071
    int i = idx & 511;
    int t = idx >> 9;

    // normalized input
    g_x[idx] = (obs[idx] - in_shift[i]) / (in_scale[i] + 1e-8f);

    // action term per (t, gate j): b_ih[j] + b_hh[j] + sum_a W_ih[j][1+a] * a_t[a]
    {
        int j = i;
        float a = b_ih[j] + b_hh[j];
        const float* wr = W_ih + j * 33 + 1;
        const float* ar = prev_act + t * 32;
#pragma unroll
        for (int aa = 0; aa < 32; aa++) a = fmaf(wr[aa], ar[aa], a);
        g_act[idx] = a;
    }

    if (idx < 512 * 128) {
        int j = idx >> 7, k = idx & 127;
        g_WhhT[k * 512 + j] = W_hh[idx];
    }
    if (idx < 128 * 128) {
        int j = idx >> 7, k = idx & 127;
        g_WkT[k * 128 + j] = Wk[idx];
    }
    if (idx < 512) g_wih0[idx] = W_ih[idx * 33];
}

// ---------------------------------------------------------------------------
// q = pos_embedding @ Wq^T + bq   (1024 x 128), computed once per launch
// ---------------------------------------------------------------------------
__global__ void q_kernel(const float* __restrict__ pe,
                         const float* __restrict__ Wq,
                         const float* __restrict__ bq) {
    int idx = blockIdx.x * blockDim.x + threadIdx.x;  // 131072
    int m = idx >> 7, j = idx & 127;
    float acc = bq[j];
    const float* per = pe + m * 128;
    const float* wr = Wq + j * 128;
#pragma unroll 4
    for (int k = 0; k < 128; k++) acc = fmaf(per[k], wr[k], acc);
    g_q[idx] = acc;
}

// ---------------------------------------------------------------------------
// Phase A: 512 independent LSTM chains. 128 CTAs x 4 neurons, 256 threads.
// Per step: gates = h @ Whh^T (+ rank-1 input + act term), LSTM update,
// k-msg = h @ Wk^T + bk -> g_K.  No inter-CTA sync needed.
// ---------------------------------------------------------------------------
__global__ __launch_bounds__(256) void lstm_kernel(const float* __restrict__ bk) {
    __shared__ float h_s[4][128];
    __shared__ float c_s[4][128];
    __shared__ float gt_s[4][512];
    __shared__ float act_s[512];
    __shared__ float wih0_s[512];
    __shared__ float bk_s[128];
    __shared__ float s_s[4];

    int tid = threadIdx.x;
    int n0 = blockIdx.x * 4;

    for (int idx = tid; idx < 512; idx += 256) {
        h_s[idx >> 7][idx & 127] = 0.0f;
        c_s[idx >> 7][idx & 127] = 0.0f;
        wih0_s[idx] = g_wih0[idx];
    }
    if (tid < 128) bk_s[tid] = bk[tid];
    __syncthreads();

    int j0 = tid, j1 = tid + 256;

    for (int t = 0; t < TT; t++) {
        for (int idx = tid; idx < 512; idx += 256) act_s[idx] = g_act[t * 512 + idx];
        if (tid < 4) s_s[tid] = g_x[t * 512 + n0 + tid];
        __syncthreads();

        // gates: 2 gate-columns per thread x 4 neurons
        float a0[4] = {0, 0, 0, 0}, a1[4] = {0, 0, 0, 0};
#pragma unroll 4
        for (int k = 0; k < 128; k++) {
            float w0 = g_WhhT[k * 512 + j0];
            float w1 = g_WhhT[k * 512 + j1];
#pragma unroll
            for (int n = 0; n < 4; n++) {
                float hv = h_s[n][k];
                a0[n] = fmaf(w0, hv, a0[n]);
                a1[n] = fmaf(w1, hv, a1[n]);
            }
        }
#pragma unroll
        for (int n = 0; n < 4; n++) {
            gt_s[n][j0] = a0[n] + s_s[n] * wih0_s[j0] + act_s[j0];
            gt_s[n][j1] = a1[n] + s_s[n] * wih0_s[j1] + act_s[j1];
        }
        __syncthreads();

        // LSTM pointwise update (torch gate order: i, f, g, o)
        for (int idx = tid; idx < 512; idx += 256) {
            int n = idx >> 7, j = idx & 127;
            float ig = gt_s[n][j];
            float fg = gt_s[n][128 + j];
            float gg = gt_s[n][256 + j];
            float og = gt_s[n][384 + j];
            float c = fsig(fg) * c_s[n][j] + fsig(ig) * ftanh(gg);
            float h = fsig(og) * ftanh(c);
            c_s[n][j] = c;
            h_s[n][j] = h;
        }
        __syncthreads();

        // key message: k = h @ Wk^T + bk  -> global
        for (int idx = tid; idx < 512; idx += 256) {
            int n = idx >> 7, j = idx & 127;
            float acc = bk_s[j];
#pragma unroll 4
            for (int k = 0; k < 128; k++) acc = fmaf(g_WkT[k * 128 + j], h_s[n][k], acc);
            g_K[(t * 512 + n0 + n) * 128 + j] = acc;
        }
        __syncthreads();
    }
}

// ---------------------------------------------------------------------------
// Phase B: out[t,m] = tanh( sum_i tanh((q[m].K[t,i])/sqrt(128)) * s[t,i] )
// grid (8 m-tiles, 256 t), 256 threads, 8x8 register tile per thread.
// smem: q tile 128x132, K chunk 128x132 (padded rows -> conflict-free LDS.128)
// ---------------------------------------------------------------------------
#define QLD 132
#define ATTN_SMEM ((2 * 128 * QLD + 512) * (int)sizeof(float))

__global__ __launch_bounds__(256) void attn_kernel(float* __restrict__ out) {
    extern __shared__ float sm[];
    float* q_s = sm;                    // 128 * QLD
    float* K_s = sm + 128 * QLD;        // 128 * QLD
    float* s_s = K_s + 128 * QLD;       // 512

    int tid = threadIdx.x;
    int mt = blockIdx.x;  // 0..7  (128 m rows each)
    int t  = blockIdx.y;  // 0..255
    int mh = tid >> 4;    // 0..15 : m sub-tile (8 contiguous m)
    int ih = tid & 15;    // 0..15 : i lane (8 strided i)

    // q tile (once per block)
    for (int f = tid; f < 128 * 32; f += 256) {
        int m = f >> 5, kq = f & 31;
        float4 v = *(const float4*)&g_q[(mt * 128 + m) * 128 + kq * 4];
        *(float4*)&q_s[m * QLD + kq * 4] = v;
    }
    for (int idx = tid; idx < 512; idx += 256) s_s[idx] = g_x[t * 512 + idx];

    float outa[8] = {0, 0, 0, 0, 0, 0, 0, 0};
    const float inv = 0.0883883476483184f;  // 1/sqrt(128)

    for (int c = 0; c < 4; c++) {
        int ibase = c * 128;
        __syncthreads();  // K_s reuse / q_s,s_s ready
        for (int f = tid; f < 128 * 32; f += 256) {
            int i = f >> 5, kq = f & 31;
            float4 v = *(const float4*)&g_K[(t * 512 + ibase + i) * 128 + kq * 4];
            *(float4*)&K_s[i * QLD + kq * 4] = v;
        }
        __syncthreads();

        float acc[8][8];
#pragma unroll
        for (int a = 0; a < 8; a++)
#pragma unroll
            for (int b = 0; b < 8; b++) acc[a][b] = 0.0f;

#pragma unroll 1
        for (int kk = 0; kk < 128; kk += 4) {
            float4 qv[8], kv[8];
#pragma unroll
            for (int r = 0; r < 8; r++) qv[r] = *(const float4*)&q_s[(mh * 8 + r) * QLD + kk];
#pragma unroll
            for (int r = 0; r < 8; r++) kv[r] = *(const float4*)&K_s[(ih + 16 * r) * QLD + kk];
#pragma unroll
            for (int a = 0; a < 8; a++)
#pragma unroll
                for (int b = 0; b < 8; b++) {
                    acc[a][b] = fmaf(qv[a].x, kv[b].x, acc[a][b]);
                    acc[a][b] = fmaf(qv[a].y, kv[b].y, acc[a][b]);
                    acc[a][b] = fmaf(qv[a].z, kv[b].z, acc[a][b]);
                    acc[a][b] = fmaf(qv[a].w, kv[b].w, acc[a][b]);
                }
        }

#pragma unroll
        for (int b = 0; b < 8; b++) {
            float sv = s_s[ibase + ih + 16 * b];
#pragma unroll
            for (int a = 0; a < 8; a++)
                outa[a] = fmaf(ftanh(acc[a][b] * inv), sv, outa[a]);
        }
    }

    // reduce over the 16 i-lanes (half-warp xor reduction)
#pragma unroll
    for (int a = 0; a < 8; a++) {
        float v = outa[a];
        v += __shfl_xor_sync(0xffffffffu, v, 1);
        v += __shfl_xor_sync(0xffffffffu, v, 2);
        v += __shfl_xor_sync(0xffffffffu, v, 4);
        v += __shfl_xor_sync(0xffffffffu, v, 8);
        if (ih == 0) out[t * 1024 + mt * 128 + mh * 8 + a] = ftanh(v);
    }
}

// ---------------------------------------------------------------------------
extern "C" void kernel_launch(void* const* d_in, const int* in_sizes, int n_in,
                              void* d_out, int out_size) {
    const float* obs      = (const float*)d_in[0];
    const float* prev_act = (const float*)d_in[1];
    const float* in_shift = (const float*)d_in[2];
    const float* in_scale = (const float*)d_in[3];
    const float* pe       = (const float*)d_in[4];
    const float* W_ih     = (const float*)d_in[5];
    const float* b_ih     = (const float*)d_in[6];
    const float* W_hh     = (const float*)d_in[7];
    const float* b_hh     = (const float*)d_in[8];
    const float* Wq       = (const float*)d_in[9];
    const float* bq       = (const float*)d_in[10];
    const float* Wk       = (const float*)d_in[11];
    const float* bk       = (const float*)d_in[12];
    float* out = (float*)d_out;

    cudaFuncSetAttribute(attn_kernel, cudaFuncAttributeMaxDynamicSharedMemorySize,
                         ATTN_SMEM);

    prep_kernel<<<512, 256>>>(obs, prev_act, in_shift, in_scale,
                              W_ih, b_ih, W_hh, b_hh, Wk);
    q_kernel<<<512, 256>>>(pe, Wq, bq);
    lstm_kernel<<<128, 256>>>(bk);
    dim3 ga(8, 256);
    attn_kernel<<<ga, 256, ATTN_SMEM>>>(out);
}

// round 2
// speedup vs baseline: 2.1866x; 2.1866x over previous
#include <cuda_runtime.h>
#include <math.h>

#define TT 256
#define OBS 512
#define HID 1024
#define MSG 128
#define PED 128

// ---- device scratch (static; no allocations) ----
__device__ float g_q[HID * MSG];                      // q = pos_emb @ Wq^T + bq
__device__ float g_K[TT * OBS * MSG];                 // 64 MB per-step key messages
__device__ float g_x[TT * OBS];                       // normalized obs
__device__ float g_act[TT * OBS];                     // b_ih+b_hh + W_ih[:,1:]@a_t
__device__ __align__(16) float g_Whh4[512 * 128];     // packed [k/4][j][4]
__device__ __align__(16) float g_Wk4[128 * 128];      // packed [k/4][j][4]
__device__ float g_wih0[512];                         // W_ih[:,0]

__device__ __forceinline__ float fsig(float x) {
    return 1.0f / (1.0f + __expf(-x));
}
__device__ __forceinline__ float ftanh(float x) {
    float t = __expf(-2.0f * fabsf(x));
    float r = (1.0f - t) / (1.0f + t);
    return copysignf(r, x);
}

// ---------------------------------------------------------------------------
// prep: normalize obs, action term, packed weight layouts, wih0
// grid: 512 x 256 = 131072 threads
// ---------------------------------------------------------------------------
__global__ void prep_kernel(const float* __restrict__ obs,
                            const float* __restrict__ prev_act,
                            const float* __restrict__ in_shift,
                            const float* __restrict__ in_scale,
                            const float* __restrict__ W_ih,
                            const float* __restrict__ b_ih,
                            const float* __restrict__ W_hh,
                            const float* __restrict__ b_hh,
                            const float* __restrict__ Wk) {
    int idx = blockIdx.x * blockDim.x + threadIdx.x;  // 0..131071
    int i = idx & 511;
    int t = idx >> 9;

    g_x[idx] = (obs[idx] - in_shift[i]) / (in_scale[i] + 1e-8f);

    {   // action term per (t, gate j)
        int j = i;
        float a = b_ih[j] + b_hh[j];
        const float* wr = W_ih + j * 33 + 1;
        const float* ar = prev_act + t * 32;
#pragma unroll
        for (int aa = 0; aa < 32; aa++) a = fmaf(wr[aa], ar[aa], a);
        g_act[idx] = a;
    }

    if (idx < 512 * 128) {  // W_hh [j][k] -> packed [k/4][j][4]
        int j = idx >> 7, k = idx & 127;
        g_Whh4[((k >> 2) * 512 + j) * 4 + (k & 3)] = W_hh[idx];
    }
    if (idx < 128 * 128) {  // Wk [j][k] -> packed [k/4][j][4]
        int j = idx >> 7, k = idx & 127;
        g_Wk4[((k >> 2) * 128 + j) * 4 + (k & 3)] = Wk[idx];
    }
    if (idx < 512) g_wih0[idx] = W_ih[idx * 33];
}

// ---------------------------------------------------------------------------
// q = pos_embedding @ Wq^T + bq   (1024 x 128)
// ---------------------------------------------------------------------------
__global__ void q_kernel(const float* __restrict__ pe,
                         const float* __restrict__ Wq,
                         const float* __restrict__ bq) {
    int idx = blockIdx.x * blockDim.x + threadIdx.x;  // 131072
    int m = idx >> 7, j = idx & 127;
    float acc = bq[j];
    const float* per = pe + m * 128;
    const float* wr = Wq + j * 128;
#pragma unroll 4
    for (int k = 0; k < 128; k++) acc = fmaf(per[k], wr[k], acc);
    g_q[idx] = acc;
}

// ---------------------------------------------------------------------------
// Phase A: 512 independent LSTM chains. 128 CTAs x 4 neurons, 512 threads.
// Coalesced float4 W streams; Wk resident in smem; 3 barriers/step.
// ---------------------------------------------------------------------------
#define LSTM_SMEM ((16384 + 2048 + 512 + 512 + 512 + 512 + 128 + 4) * (int)sizeof(float))

__global__ __launch_bounds__(512) void lstm_kernel(const float* __restrict__ bk) {
    extern __shared__ float sm[];
    float* Wk_s   = sm;              // 16384 : packed [k/4][j][4]
    float* gt_s   = Wk_s + 16384;    // 2048  : [n][512]
    float* h_s    = gt_s + 2048;     // 512   : [n][128]
    float* c_s    = h_s + 512;       // 512
    float* act_s  = c_s + 512;       // 512
    float* wih0_s = act_s + 512;     // 512
    float* bk_s   = wih0_s + 512;    // 128
    float* s_s    = bk_s + 128;      // 4

    int tid = threadIdx.x;           // 0..511
    int n0 = blockIdx.x * 4;

    // one-time staging
    {
        const float4* src = (const float4*)g_Wk4;
        float4* dst = (float4*)Wk_s;
#pragma unroll
        for (int f = 0; f < 8; f++) dst[tid + f * 512] = src[tid + f * 512];
    }
    if (tid < 512) {
        h_s[tid & 511] = 0.0f;  // (tid<512 always true; keep simple)
        c_s[tid] = 0.0f;
        wih0_s[tid] = g_wih0[tid];
    }
    if (tid < 128) bk_s[tid] = bk[tid];
    __syncthreads();

    const float4* Whh = (const float4*)g_Whh4;  // [k4*512 + j]
    int j = tid;

    for (int t = 0; t < TT; t++) {
        act_s[j] = g_act[t * 512 + j];
        if (tid < 4) s_s[tid] = g_x[t * 512 + n0 + tid];
        __syncthreads();

        // ---- gate GEMM: thread j computes gate column j for 4 neurons ----
        float a0, a1, a2, a3;
        {
            float aj = act_s[j], wj = wih0_s[j];
            a0 = fmaf(s_s[0], wj, aj);
            a1 = fmaf(s_s[1], wj, aj);
            a2 = fmaf(s_s[2], wj, aj);
            a3 = fmaf(s_s[3], wj, aj);
        }
#pragma unroll 4
        for (int k4 = 0; k4 < 32; k4++) {
            float4 w = Whh[k4 * 512 + j];
            float4 h0 = *(const float4*)&h_s[0 * 128 + k4 * 4];
            float4 h1 = *(const float4*)&h_s[1 * 128 + k4 * 4];
            float4 h2 = *(const float4*)&h_s[2 * 128 + k4 * 4];
            float4 h3 = *(const float4*)&h_s[3 * 128 + k4 * 4];
            a0 = fmaf(w.x, h0.x, a0); a0 = fmaf(w.y, h0.y, a0);
            a0 = fmaf(w.z, h0.z, a0); a0 = fmaf(w.w, h0.w, a0);
            a1 = fmaf(w.x, h1.x, a1); a1 = fmaf(w.y, h1.y, a1);
            a1 = fmaf(w.z, h1.z, a1); a1 = fmaf(w.w, h1.w, a1);
            a2 = fmaf(w.x, h2.x, a2); a2 = fmaf(w.y, h2.y, a2);
            a2 = fmaf(w.z, h2.z, a2); a2 = fmaf(w.w, h2.w, a2);
            a3 = fmaf(w.x, h3.x, a3); a3 = fmaf(w.y, h3.y, a3);
            a3 = fmaf(w.z, h3.z, a3); a3 = fmaf(w.w, h3.w, a3);
        }
        gt_s[0 * 512 + j] = a0;
        gt_s[1 * 512 + j] = a1;
        gt_s[2 * 512 + j] = a2;
        gt_s[3 * 512 + j] = a3;
        __syncthreads();

        // ---- LSTM pointwise (torch gate order i,f,g,o) ----
        {
            int n = tid >> 7, jj = tid & 127;
            float ig = gt_s[n * 512 + jj];
            float fg = gt_s[n * 512 + 128 + jj];
            float gg = gt_s[n * 512 + 256 + jj];
            float og = gt_s[n * 512 + 384 + jj];
            float c = fsig(fg) * c_s[tid] + fsig(ig) * ftanh(gg);
            float h = fsig(og) * ftanh(c);
            c_s[tid] = c;
            h_s[tid] = h;
        }
        __syncthreads();

        // ---- key message: k = h @ Wk^T + bk ----
        {
            int n = tid >> 7, jj = tid & 127;
            float acc = bk_s[jj];
#pragma unroll 4
            for (int k4 = 0; k4 < 32; k4++) {
                float4 w = *(const float4*)&Wk_s[(k4 * 128 + jj) * 4];
                float4 hv = *(const float4*)&h_s[n * 128 + k4 * 4];
                acc = fmaf(w.x, hv.x, acc);
                acc = fmaf(w.y, hv.y, acc);
                acc = fmaf(w.z, hv.z, acc);
                acc = fmaf(w.w, hv.w, acc);
            }
            g_K[(t * 512 + n0 + n) * 128 + jj] = acc;
        }
        __syncthreads();
    }
}

// ---------------------------------------------------------------------------
// Phase B: out[t,m] = tanh( sum_i tanh((q[m].K[t,i])/sqrt(128)) * s[t,i] )
// ---------------------------------------------------------------------------
#define QLD 132
#define ATTN_SMEM ((2 * 128 * QLD + 512) * (int)sizeof(float))

__global__ __launch_bounds__(256) void attn_kernel(float* __restrict__ out) {
    extern __shared__ float sm[];
    float* q_s = sm;                    // 128 * QLD
    float* K_s = sm + 128 * QLD;        // 128 * QLD
    float* s_s = K_s + 128 * QLD;       // 512

    int tid = threadIdx.x;
    int mt = blockIdx.x;  // 0..7
    int t  = blockIdx.y;  // 0..255
    int mh = tid >> 4;
    int ih = tid & 15;

    for (int f = tid; f < 128 * 32; f += 256) {
        int m = f >> 5, kq = f & 31;
        float4 v = *(const float4*)&g_q[(mt * 128 + m) * 128 + kq * 4];
        *(float4*)&q_s[m * QLD + kq * 4] = v;
    }
    for (int idx = tid; idx < 512; idx += 256) s_s[idx] = g_x[t * 512 + idx];

    float outa[8] = {0, 0, 0, 0, 0, 0, 0, 0};
    const float inv = 0.0883883476483184f;

    for (int c = 0; c < 4; c++) {
        int ibase = c * 128;
        __syncthreads();
        for (int f = tid; f < 128 * 32; f += 256) {
            int i = f >> 5, kq = f & 31;
            float4 v = *(const float4*)&g_K[(t * 512 + ibase + i) * 128 + kq * 4];
            *(float4*)&K_s[i * QLD + kq * 4] = v;
        }
        __syncthreads();

        float acc[8][8];
#pragma unroll
        for (int a = 0; a < 8; a++)
#pragma unroll
            for (int b = 0; b < 8; b++) acc[a][b] = 0.0f;

#pragma unroll 1
        for (int kk = 0; kk < 128; kk += 4) {
            float4 qv[8], kv[8];
#pragma unroll
            for (int r = 0; r < 8; r++) qv[r] = *(const float4*)&q_s[(mh * 8 + r) * QLD + kk];
#pragma unroll
            for (int r = 0; r < 8; r++) kv[r] = *(const float4*)&K_s[(ih + 16 * r) * QLD + kk];
#pragma unroll
            for (int a = 0; a < 8; a++)
#pragma unroll
                for (int b = 0; b < 8; b++) {
                    acc[a][b] = fmaf(qv[a].x, kv[b].x, acc[a][b]);
                    acc[a][b] = fmaf(qv[a].y, kv[b].y, acc[a][b]);
                    acc[a][b] = fmaf(qv[a].z, kv[b].z, acc[a][b]);
                    acc[a][b] = fmaf(qv[a].w, kv[b].w, acc[a][b]);
                }
        }

#pragma unroll
        for (int b = 0; b < 8; b++) {
            float sv = s_s[ibase + ih + 16 * b];
#pragma unroll
            for (int a = 0; a < 8; a++)
                outa[a] = fmaf(ftanh(acc[a][b] * inv), sv, outa[a]);
        }
    }

#pragma unroll
    for (int a = 0; a < 8; a++) {
        float v = outa[a];
        v += __shfl_xor_sync(0xffffffffu, v, 1);
        v += __shfl_xor_sync(0xffffffffu, v, 2);
        v += __shfl_xor_sync(0xffffffffu, v, 4);
        v += __shfl_xor_sync(0xffffffffu, v, 8);
        if (ih == 0) out[t * 1024 + mt * 128 + mh * 8 + a] = ftanh(v);
    }
}

// ---------------------------------------------------------------------------
extern "C" void kernel_launch(void* const* d_in, const int* in_sizes, int n_in,
                              void* d_out, int out_size) {
    const float* obs      = (const float*)d_in[0];
    const float* prev_act = (const float*)d_in[1];
    const float* in_shift = (const float*)d_in[2];
    const float* in_scale = (const float*)d_in[3];
    const float* pe       = (const float*)d_in[4];
    const float* W_ih     = (const float*)d_in[5];
    const float* b_ih     = (const float*)d_in[6];
    const float* W_hh     = (const float*)d_in[7];
    const float* b_hh     = (const float*)d_in[8];
    const float* Wq       = (const float*)d_in[9];
    const float* bq       = (const float*)d_in[10];
    const float* Wk       = (const float*)d_in[11];
    const float* bk       = (const float*)d_in[12];
    float* out = (float*)d_out;

    cudaFuncSetAttribute(attn_kernel, cudaFuncAttributeMaxDynamicSharedMemorySize,
                         ATTN_SMEM);
    cudaFuncSetAttribute(lstm_kernel, cudaFuncAttributeMaxDynamicSharedMemorySize,
                         LSTM_SMEM);

    prep_kernel<<<512, 256>>>(obs, prev_act, in_shift, in_scale,
                              W_ih, b_ih, W_hh, b_hh, Wk);
    q_kernel<<<512, 256>>>(pe, Wq, bq);
    lstm_kernel<<<128, 512, LSTM_SMEM>>>(bk);
    dim3 ga(8, 256);
    attn_kernel<<<ga, 256, ATTN_SMEM>>>(out);
}